// round 15
// baseline (speedup 1.0000x reference)
#include <cuda_runtime.h>
#include <cuda_fp16.h>
#include <cstdint>

// ---------------- configuration ----------------
#define TOK_TILE     64
#define NUM_TILES    256          // 16384 / 64 -> 2 CTAs resident per SM
#define THREADS      256          // 8 warps: 2 m-groups x 4 n-groups (Mw=32, Nw=16)
#define KB_STEPS     8            // K=256 in blocks of 32
#define NSLICES      512
#define SLICE_WORDS  1024         // 64 o x 32 k halves = 1024 b32 words
#define PF           3            // prefetch distance (chunks), ring of 4

// smem: x2 tile as duplicated-f16x2 (one u32 per (t,c))
#define X2D_STRIDE   65
#define SMEM_BYTES   (TOK_TILE * X2D_STRIDE * 4)   // 16640

// W slices (512 x 1024 words) + bias matrix (2 x 1024 words) fragment-ordered
__device__ uint32_t g_Wh[4096 * 128 + 2048];

static __device__ __forceinline__ uint32_t pack_h2(float lo, float hi) {
    uint32_t r;
    asm("cvt.rn.f16x2.f32 %0, %1, %2;" : "=r"(r) : "f"(hi), "f"(lo));
    return r;
}
static __device__ __forceinline__ uint32_t hmul2(uint32_t a, uint32_t b) {
    uint32_t r;
    asm("mul.rn.f16x2 %0, %1, %2;" : "=r"(r) : "r"(a), "r"(b));
    return r;
}
// D(f32x4) += A(f16)xB(f16)  -- accumulator never leaves the chain
static __device__ __forceinline__ void mma_acc(float& d0, float& d1, float& d2, float& d3,
                                               const uint32_t* a, uint32_t b0, uint32_t b1) {
    asm("mma.sync.aligned.m16n8k16.row.col.f32.f16.f16.f32 "
        "{%0,%1,%2,%3}, {%4,%5,%6,%7}, {%8,%9}, {%0,%1,%2,%3};"
        : "+f"(d0), "+f"(d1), "+f"(d2), "+f"(d3)
        : "r"(a[0]), "r"(a[1]), "r"(a[2]), "r"(a[3]), "r"(b0), "r"(b1));
}

// -------- W pre-transform: fp32 -> f16x2, fragment order (proven layout) --------
__global__ void prep_kernel(const float* __restrict__ W) {
    int idx = blockIdx.x * 256 + threadIdx.x;      // 524,288 threads
    int s   = idx >> 10;
    int rem = idx & 1023;
    int o   = rem >> 4;
    int r   = (rem >> 2) & 3;
    int q   = rem & 3;
    int ks  = q >> 1, hb = q & 1;
    int kb  = s >> 6, c = s & 63;
    const float* src = W + (size_t)(c * 64 + o) * 256 + kb * 32 + ks * 16 + hb * 8 + r * 2;
    g_Wh[idx] = pack_h2(src[0], src[1]);
}

// -------- bias matrix Bm[c][o] = bvec[c*64+o] as 2 fragment-ordered pseudo-slices --------
__global__ void prep_bias(const float* __restrict__ bvec) {
    int idx = threadIdx.x + blockIdx.x * 256;      // 2048 threads
    int kh  = idx >> 10;
    int rem = idx & 1023;
    int o   = rem >> 4;
    int r   = (rem >> 2) & 3;
    int q   = rem & 3;
    int ks  = q >> 1, hb = q & 1;
    int k0  = kh * 32 + ks * 16 + hb * 8 + r * 2;  // k0 = c index
    g_Wh[4096 * 128 + idx] = pack_h2(bvec[k0 * 64 + o], bvec[(k0 + 1) * 64 + o]);
}

// this warp's B fragments for slice s: 1 LDG.128 per nt, fully coalesced
static __device__ __forceinline__ void load_frags(uint32_t bf[2][4], int s,
                                                  int cn, int gID, int tig) {
    const uint4* base = reinterpret_cast<const uint4*>(g_Wh) + (size_t)s * (SLICE_WORDS / 4);
#pragma unroll
    for (int nt = 0; nt < 2; nt++) {
        int o = cn + nt * 8 + gID;
        uint4 v = __ldg(base + o * 4 + tig);
        bf[nt][0] = v.x; bf[nt][1] = v.y; bf[nt][2] = v.z; bf[nt][3] = v.w;
    }
}

// A fragments (src -> fp16) for one 32-wide k block; generic row stride
static __device__ __forceinline__ void load_A(uint32_t A[2][2][4],
                                              const float* __restrict__ src,
                                              int row0, int row_stride, int k_base,
                                              int rm, int gID, int tig) {
#pragma unroll
    for (int mt = 0; mt < 2; mt++) {
        const float* r0 = src + (size_t)(row0 + rm + mt * 16 + gID) * row_stride + k_base;
        const float* r1 = r0 + 8 * row_stride;
#pragma unroll
        for (int ks = 0; ks < 2; ks++) {
            int k0 = ks * 16 + tig * 2;
            float2 a0 = *reinterpret_cast<const float2*>(r0 + k0);
            float2 a1 = *reinterpret_cast<const float2*>(r1 + k0);
            float2 a2 = *reinterpret_cast<const float2*>(r0 + k0 + 8);
            float2 a3 = *reinterpret_cast<const float2*>(r1 + k0 + 8);
            A[mt][ks][0] = pack_h2(a0.x, a0.y);
            A[mt][ks][1] = pack_h2(a1.x, a1.y);
            A[mt][ks][2] = pack_h2(a2.x, a2.y);
            A[mt][ks][3] = pack_h2(a3.x, a3.y);
        }
    }
}

// one chunk: scale A by x2[t,c] (fma pipe) then 8 HMMA into persistent f32 D
static __device__ __forceinline__ void chunk_mma(
    const uint32_t bf[2][4], const uint32_t* __restrict__ x2ds,
    const uint32_t A[2][2][4], float D[2][2][4],
    int c, int rm, int gID)
{
#pragma unroll
    for (int mt = 0; mt < 2; mt++) {
        uint32_t xq0 = x2ds[(rm + mt * 16 + gID) * X2D_STRIDE + c];
        uint32_t xq1 = x2ds[(rm + mt * 16 + gID + 8) * X2D_STRIDE + c];
        uint32_t Ap[2][4];
#pragma unroll
        for (int ks = 0; ks < 2; ks++) {
            Ap[ks][0] = hmul2(A[mt][ks][0], xq0);
            Ap[ks][1] = hmul2(A[mt][ks][1], xq1);
            Ap[ks][2] = hmul2(A[mt][ks][2], xq0);
            Ap[ks][3] = hmul2(A[mt][ks][3], xq1);
        }
#pragma unroll
        for (int nt = 0; nt < 2; nt++) {
            mma_acc(D[mt][nt][0], D[mt][nt][1], D[mt][nt][2], D[mt][nt][3],
                    Ap[0], bf[nt][0], bf[nt][1]);
            mma_acc(D[mt][nt][0], D[mt][nt][1], D[mt][nt][2], D[mt][nt][3],
                    Ap[1], bf[nt][2], bf[nt][3]);
        }
    }
}

__global__ void __launch_bounds__(THREADS, 2)
metaLinear_kernel(const float* __restrict__ x1, const float* __restrict__ x2,
                  float* __restrict__ out)
{
    extern __shared__ uint32_t x2ds[];

    const int tid  = threadIdx.x;
    const int lane = tid & 31, wid = tid >> 5;
    const int wm = wid >> 2, wn = wid & 3;          // 2 m-groups x 4 n-groups
    const int gID = lane >> 2, tig = lane & 3;
    const int tok0 = blockIdx.x * TOK_TILE;
    const int rm = wm * 32;
    const int cn = wn * 16;

    // x2 tile -> smem as duplicated f16x2; the ONLY block barrier
    for (int i = tid; i < TOK_TILE * 64; i += THREADS) {
        int r = i >> 6, c = i & 63;
        float v = x2[(size_t)(tok0 + r) * 64 + c];
        x2ds[r * X2D_STRIDE + c] = pack_h2(v, v);
    }

    uint32_t A[2][2][4];
    float D[2][2][4];
#pragma unroll
    for (int mt = 0; mt < 2; mt++)
#pragma unroll
        for (int nt = 0; nt < 2; nt++)
#pragma unroll
            for (int j = 0; j < 4; j++) D[mt][nt][j] = 0.0f;

    load_A(A, x1, tok0, 256, 0, rm, gID, tig);

    // B-fragment ring: 4 buffers, prefetch distance PF=3
    uint32_t bf[4][2][4];
    load_frags(bf[0], 0, cn, gID, tig);
    load_frags(bf[1], 1, cn, gID, tig);
    load_frags(bf[2], 2, cn, gID, tig);

    __syncthreads();   // x2ds visible

    // free-running main loop: no drains, deep register prefetch
    for (int s = 0; s < NSLICES; s += 4) {
        const int kb = s >> 6;
        const int c  = s & 63;

#pragma unroll
        for (int u = 0; u < 4; u++) {
            int sp = s + u + PF;
            load_frags(bf[(s + u + PF) & 3], (sp < NSLICES) ? sp : NSLICES - 1,
                       cn, gID, tig);
            chunk_mma(bf[(s + u) & 3], x2ds, A, D, c + u, rm, gID);
        }

        if (c == 60 && kb + 1 < KB_STEPS)
            load_A(A, x1, tok0, 256, (kb + 1) * 32, rm, gID, tig);
    }

    // bias: y += x2 . Bm  (two k32 pseudo-chunks, A = x2 fragments, no scaling)
#pragma unroll
    for (int kh = 0; kh < 2; kh++) {
        uint32_t Ab[2][2][4];
        load_A(Ab, x2, tok0, 64, kh * 32, rm, gID, tig);
        uint32_t bfb[2][4];
        load_frags(bfb, 512 + kh, cn, gID, tig);
#pragma unroll
        for (int mt = 0; mt < 2; mt++)
#pragma unroll
            for (int nt = 0; nt < 2; nt++) {
                mma_acc(D[mt][nt][0], D[mt][nt][1], D[mt][nt][2], D[mt][nt][3],
                        Ab[mt][0], bfb[nt][0], bfb[nt][1]);
                mma_acc(D[mt][nt][0], D[mt][nt][1], D[mt][nt][2], D[mt][nt][3],
                        Ab[mt][1], bfb[nt][2], bfb[nt][3]);
            }
    }

    // write y: d0,d1 = row gID cols (tig*2, tig*2+1); d2,d3 = row gID+8
#pragma unroll
    for (int mt = 0; mt < 2; mt++)
#pragma unroll
        for (int h = 0; h < 2; h++) {
            int row = tok0 + rm + mt * 16 + gID + h * 8;
#pragma unroll
            for (int nt = 0; nt < 2; nt++) {
                float2 v;
                v.x = D[mt][nt][h * 2 + 0];
                v.y = D[mt][nt][h * 2 + 1];
                *reinterpret_cast<float2*>(
                    out + (size_t)row * 64 + cn + nt * 8 + tig * 2) = v;
            }
        }
}

extern "C" void kernel_launch(void* const* d_in, const int* in_sizes, int n_in,
                              void* d_out, int out_size) {
    const float* x1   = (const float*)d_in[0];
    const float* x2   = (const float*)d_in[1];
    const float* W    = (const float*)d_in[2];
    const float* bvec = (const float*)d_in[3];
    float* out = (float*)d_out;
    (void)in_sizes; (void)n_in; (void)out_size;

    prep_kernel<<<2048, 256>>>(W);
    prep_bias<<<8, 256>>>(bvec);
    metaLinear_kernel<<<NUM_TILES, THREADS, SMEM_BYTES>>>(x1, x2, out);
}